// round 14
// baseline (speedup 1.0000x reference)
#include <cuda_runtime.h>
#include <cuda_fp16.h>
#include <math.h>
#include <stdint.h>

// ---------------------------------------------------------------------------
#define NSEQ 2048
#define DMODEL 1024
#define NHEAD 16
#define HDIM 64
#define DFF 4096
#define NOFF 44
#define D3 (3 * DMODEL)
#define DQG 4096          // qkv + gate combined width

__constant__ int c_offs[NOFF] = {
    0,1,2,3,4,5,6,7,8,9,10,11,12,13,14,15,16,17,18,19,20,21,22,23,24,25,26,27,
    28,29,30,31,32,48,64,96,128,192,256,384,512,768,1024,1536};

// ---------------------------------------------------------------------------
// Scratch
// ---------------------------------------------------------------------------
__device__ __half g_xn [NSEQ * DMODEL];
__device__ __half g_qg [NSEQ * DQG];      // [q|k|v|gate] fp16
__device__ __half g_y  [NSEQ * DMODEL];
__device__ float  g_x1 [NSEQ * DMODEL];
__device__ __half g_xn2[NSEQ * DMODEL];
__device__ __half g_h  [NSEQ * DFF];
__device__ __half g_wqg [DQG * DMODEL];
__device__ __half g_wout[DMODEL * DMODEL];
__device__ __half g_wfc1[DFF * DMODEL];
__device__ __half g_wfc2[DMODEL * DFF];
__device__ float  g_bqg [DQG];

// ---------------------------------------------------------------------------
__device__ __forceinline__ uint32_t smem_u32(const void* p) {
    uint32_t a;
    asm("{ .reg .u64 t; cvta.to.shared.u64 t, %1; cvt.u32.u64 %0, t; }"
        : "=r"(a) : "l"(p));
    return a;
}

#define CPA16(dst, src) \
    asm volatile("cp.async.cg.shared.global [%0], [%1], 16;\n" :: "r"(dst), "l"(src))

#define LDSM_X4(r0, r1, r2, r3, addr) \
    asm volatile("ldmatrix.sync.aligned.m8n8.x4.shared.b16 {%0,%1,%2,%3}, [%4];" \
        : "=r"(r0), "=r"(r1), "=r"(r2), "=r"(r3) : "r"(addr))

__device__ __forceinline__ float2 h2f2(uint32_t u) {
    __half2 h = *(__half2*)&u;
    return __half22float2(h);
}

// ---------------------------------------------------------------------------
// Weight prep: [K,N]fp32 -> [N,K]fp16, 64k x 32n tiles.
// Reads 128B rows (32 floats), writes 128B rows (64 halves) — both coalesced.
// blocks: qkv 1536 | gate 512 | out 512 | fc1 2048 | fc2 2048 = 6656
// ---------------------------------------------------------------------------
__global__ void prep_kernel(const float* __restrict__ qkv_w,
                            const float* __restrict__ gate_w,
                            const float* __restrict__ out_w,
                            const float* __restrict__ fc1_w,
                            const float* __restrict__ fc2_w) {
    __shared__ float t[64][33];
    int bid = blockIdx.x;
    const float* W; __half* Wt; int K, Nw, b;
    if (bid < 1536)       { b = bid;        W = qkv_w;  Wt = g_wqg;                       K = 1024; Nw = 3072; }
    else if (bid < 2048)  { b = bid - 1536; W = gate_w; Wt = g_wqg + (size_t)3072 * 1024; K = 1024; Nw = 1024; }
    else if (bid < 2560)  { b = bid - 2048; W = out_w;  Wt = g_wout;                      K = 1024; Nw = 1024; }
    else if (bid < 4608)  { b = bid - 2560; W = fc1_w;  Wt = g_wfc1;                      K = 1024; Nw = 4096; }
    else                  { b = bid - 4608; W = fc2_w;  Wt = g_wfc2;                      K = 4096; Nw = 1024; }
    int nx = Nw >> 5;
    int n0 = (b % nx) * 32, k0 = (b / nx) * 64;
    int tx = threadIdx.x, ty = threadIdx.y;   // (32, 8)
    #pragma unroll
    for (int i = 0; i < 8; i++) {
        int kr = ty + i * 8;
        t[kr][tx] = W[(size_t)(k0 + kr) * Nw + n0 + tx];
    }
    __syncthreads();
    #pragma unroll
    for (int i = 0; i < 4; i++) {
        int nr = ty + i * 8;
        __half2 hv = __floats2half2_rn(t[tx * 2][nr], t[tx * 2 + 1][nr]);
        *(__half2*)(Wt + (size_t)(n0 + nr) * K + k0 + tx * 2) = hv;
    }
}

__global__ void bias_cat(const float* __restrict__ qkv_b,
                         const float* __restrict__ gate_b) {
    int i = blockIdx.x * 256 + threadIdx.x;
    if (i < DQG) g_bqg[i] = (i < D3) ? qkv_b[i] : gate_b[i - D3];
}

// ---------------------------------------------------------------------------
// LayerNorm -> fp16
// ---------------------------------------------------------------------------
__global__ void ln_kernel(const float* __restrict__ x,
                          const float* __restrict__ g,
                          const float* __restrict__ b,
                          __half* __restrict__ out) {
    int row = blockIdx.x;
    int tid = threadIdx.x;
    const float4* xr = (const float4*)(x + (size_t)row * DMODEL);
    float4 v = xr[tid];
    float s  = v.x + v.y + v.z + v.w;
    float sq = v.x * v.x + v.y * v.y + v.z * v.z + v.w * v.w;
    #pragma unroll
    for (int o = 16; o > 0; o >>= 1) {
        s  += __shfl_xor_sync(0xffffffffu, s,  o);
        sq += __shfl_xor_sync(0xffffffffu, sq, o);
    }
    __shared__ float sh[16];
    int wid = tid >> 5, lane = tid & 31;
    if (lane == 0) { sh[wid] = s; sh[wid + 8] = sq; }
    __syncthreads();
    float ts = 0.f, tq = 0.f;
    #pragma unroll
    for (int w = 0; w < 8; w++) { ts += sh[w]; tq += sh[w + 8]; }
    float mu  = ts * (1.0f / DMODEL);
    float var = tq * (1.0f / DMODEL) - mu * mu;
    var = var > 0.f ? var : 0.f;
    float rstd = rsqrtf(var + 1e-5f);

    float4 gv = ((const float4*)g)[tid];
    float4 bv = ((const float4*)b)[tid];
    __half2 h0 = __floats2half2_rn((v.x - mu) * rstd * gv.x + bv.x,
                                   (v.y - mu) * rstd * gv.y + bv.y);
    __half2 h1 = __floats2half2_rn((v.z - mu) * rstd * gv.z + bv.z,
                                   (v.w - mu) * rstd * gv.w + bv.w);
    uint2 o;
    o.x = *(uint32_t*)&h0;
    o.y = *(uint32_t*)&h1;
    *(uint2*)(out + (size_t)row * DMODEL + tid * 4) = o;
}

// ---------------------------------------------------------------------------
// fp16 tile loader: ROWS x 64 halves, row stride 144B
// ---------------------------------------------------------------------------
template <int ROWS, int NT>
__device__ __forceinline__ void tile_load(uint32_t dst, const __half* src,
                                          int ldK, int tid) {
    #pragma unroll
    for (int i = 0; i < ROWS * 8 / NT; i++) {
        int c = i * NT + tid;
        int m = c >> 3, q = c & 7;
        CPA16(dst + (uint32_t)(m * 144 + q * 16), src + (size_t)m * ldK + q * 8);
    }
}

// ---------------------------------------------------------------------------
// fp16 GEMM (R9-exact pipeline): 2-stage cp.async; per kt: wait-all, sync,
// commit prefetch, compute, sync.
//   EPI 2: +bias+res(fp32)->fp32 | 3: gelu->fp16 | 4: qkv|gate mixed ->fp16
// ---------------------------------------------------------------------------
template <int BM, int BN, int WM, int WN, int EPI, bool OUTH>
__global__ void __launch_bounds__(WM * WN * 32, 4)
hgemm(const __half* __restrict__ A, const __half* __restrict__ Bt,
      const float* __restrict__ bias, const float* __restrict__ res,
      void* __restrict__ Cv, int N, int K) {
    constexpr int NT = WM * WN * 32;
    constexpr int MI = BM / WM / 16;
    constexpr int NI = BN / WN / 8;
    constexpr int NJ = NI / 2;
    constexpr uint32_t ASTAGE = BM * 144;
    constexpr uint32_t BSTAGE = BN * 144;

    extern __shared__ char dsm[];

    const int tid  = threadIdx.x;
    const int warp = tid >> 5, lane = tid & 31;
    const int g    = lane >> 2, t4 = lane & 3;
    const int warpM = (warp / WN) * (BM / WM);
    const int warpN = (warp % WN) * (BN / WN);
    const int rowBase = blockIdx.y * BM;
    const int colBase = blockIdx.x * BN;

    const uint32_t smA = smem_u32(dsm);
    const uint32_t smB = smA + 2 * ASTAGE;
    const uint32_t aLds = smA + (uint32_t)((warpM + (lane & 15)) * 144 + (lane >> 4) * 16);
    const uint32_t bLds = smB + (uint32_t)((warpN + (lane & 15)) * 144 + (lane >> 4) * 16);

    const __half* Ag = A + (size_t)rowBase * K;
    const __half* Bg = Bt + (size_t)colBase * K;

    float acc[MI][NI][4];
    #pragma unroll
    for (int mi = 0; mi < MI; mi++)
        #pragma unroll
        for (int ni = 0; ni < NI; ni++)
            #pragma unroll
            for (int r = 0; r < 4; r++) acc[mi][ni][r] = 0.f;

    const int KT = K / 64;
    tile_load<BM, NT>(smA, Ag, K, tid);
    tile_load<BN, NT>(smB, Bg, K, tid);
    asm volatile("cp.async.commit_group;\n");

    for (int kt = 0; kt < KT; kt++) {
        asm volatile("cp.async.wait_group 0;\n");
        __syncthreads();

        if (kt + 1 < KT) {
            const uint32_t nb = (uint32_t)((kt + 1) & 1);
            tile_load<BM, NT>(smA + nb * ASTAGE, Ag + (kt + 1) * 64, K, tid);
            tile_load<BN, NT>(smB + nb * BSTAGE, Bg + (kt + 1) * 64, K, tid);
            asm volatile("cp.async.commit_group;\n");
        }

        const uint32_t aOff = aLds + (uint32_t)(kt & 1) * ASTAGE;
        const uint32_t bOff = bLds + (uint32_t)(kt & 1) * BSTAGE;
        #pragma unroll
        for (int ks = 0; ks < 4; ks++) {
            uint32_t af[MI][4], bf[NJ][4];
            #pragma unroll
            for (int mi = 0; mi < MI; mi++)
                LDSM_X4(af[mi][0], af[mi][1], af[mi][2], af[mi][3],
                        aOff + (uint32_t)(mi * 16 * 144 + ks * 32));
            #pragma unroll
            for (int nj = 0; nj < NJ; nj++)
                LDSM_X4(bf[nj][0], bf[nj][1], bf[nj][2], bf[nj][3],
                        bOff + (uint32_t)(nj * 16 * 144 + ks * 32));
            #pragma unroll
            for (int mi = 0; mi < MI; mi++)
                #pragma unroll
                for (int nj = 0; nj < NJ; nj++) {
                    asm volatile(
                        "mma.sync.aligned.m16n8k16.row.col.f32.f16.f16.f32 "
                        "{%0,%1,%2,%3}, {%4,%5,%6,%7}, {%8,%9}, {%0,%1,%2,%3};\n"
                        : "+f"(acc[mi][2*nj][0]), "+f"(acc[mi][2*nj][1]),
                          "+f"(acc[mi][2*nj][2]), "+f"(acc[mi][2*nj][3])
                        : "r"(af[mi][0]), "r"(af[mi][1]), "r"(af[mi][2]), "r"(af[mi][3]),
                          "r"(bf[nj][0]), "r"(bf[nj][2]));
                    asm volatile(
                        "mma.sync.aligned.m16n8k16.row.col.f32.f16.f16.f32 "
                        "{%0,%1,%2,%3}, {%4,%5,%6,%7}, {%8,%9}, {%0,%1,%2,%3};\n"
                        : "+f"(acc[mi][2*nj+1][0]), "+f"(acc[mi][2*nj+1][1]),
                          "+f"(acc[mi][2*nj+1][2]), "+f"(acc[mi][2*nj+1][3])
                        : "r"(af[mi][0]), "r"(af[mi][1]), "r"(af[mi][2]), "r"(af[mi][3]),
                          "r"(bf[nj][1]), "r"(bf[nj][3]));
                }
        }
        __syncthreads();
    }

    const bool sig = (EPI == 4) && (colBase >= D3);
    #pragma unroll
    for (int mi = 0; mi < MI; mi++) {
        #pragma unroll
        for (int ni = 0; ni < NI; ni++) {
            int row = rowBase + warpM + mi * 16 + g;
            int col = colBase + warpN + ni * 8 + t4 * 2;
            float b0 = bias[col], b1 = bias[col + 1];
            #pragma unroll
            for (int hh = 0; hh < 2; hh++) {
                int r = row + hh * 8;
                float vx = acc[mi][ni][hh * 2 + 0] + b0;
                float vy = acc[mi][ni][hh * 2 + 1] + b1;
                if (EPI == 3) {
                    vx = 0.5f * vx * (1.0f + erff(vx * 0.70710678118654752f));
                    vy = 0.5f * vy * (1.0f + erff(vy * 0.70710678118654752f));
                } else if (EPI == 4) {
                    if (sig) {
                        vx = 1.0f / (1.0f + __expf(-vx));
                        vy = 1.0f / (1.0f + __expf(-vy));
                    }
                }
                size_t off = (size_t)r * N + col;
                if (EPI == 2) {
                    float2 rr = *(const float2*)(res + off);
                    vx += rr.x; vy += rr.y;
                }
                if (OUTH) {
                    __half2 hv = __floats2half2_rn(vx, vy);
                    *(__half2*)((__half*)Cv + off) = hv;
                } else {
                    *(float2*)((float*)Cv + off) = make_float2(vx, vy);
                }
            }
        }
    }
}

// ---------------------------------------------------------------------------
// Offset attention on combined [q|k|v|gate] buffer (stride DQG).
// ---------------------------------------------------------------------------
__global__ void attn_kernel(const __half* __restrict__ qg,
                            const float* __restrict__ pos_bias,
                            __half* __restrict__ y) {
    int warp = blockIdx.x * (blockDim.x >> 5) + (threadIdx.x >> 5);
    int lane = threadIdx.x & 31;
    int h = warp >> 11;
    int n = warp & 2047;
    int j = lane & 7;
    int g = lane >> 3;

    const __half* qrow  = qg + (size_t)n * DQG + h * HDIM + j * 8;
    const __half* kbase = qg + DMODEL + h * HDIM + j * 8;
    const __half* vbase = qg + 2 * DMODEL + h * HDIM + j * 8;
    const __half* gbase = qg + 3 * DMODEL + h * HDIM + j * 8;

    uint4 qv = *(const uint4*)(qrow);
    float2 q0 = h2f2(qv.x), q1 = h2f2(qv.y), q2 = h2f2(qv.z), q3 = h2f2(qv.w);

    const float scale = 0.125f;
    float s[11];

    #pragma unroll
    for (int i = 0; i < 11; i++) {
        int o = i * 4 + g;
        int delta = c_offs[o];
        bool valid = (delta <= n);
        float p = 0.f;
        if (valid) {
            uint4 kv = *(const uint4*)(kbase + (size_t)(n - delta) * DQG);
            float2 k0 = h2f2(kv.x), k1 = h2f2(kv.y), k2 = h2f2(kv.z), k3 = h2f2(kv.w);
            p = q0.x * k0.x + q0.y * k0.y + q1.x * k1.x + q1.y * k1.y
              + q2.x * k2.x + q2.y * k2.y + q3.x * k3.x + q3.y * k3.y;
        }
        p += __shfl_xor_sync(0xffffffffu, p, 1);
        p += __shfl_xor_sync(0xffffffffu, p, 2);
        p += __shfl_xor_sync(0xffffffffu, p, 4);
        s[i] = valid ? p * scale + pos_bias[o * NHEAD + h] : -INFINITY;
    }

    float mx = s[0];
    #pragma unroll
    for (int i = 1; i < 11; i++) mx = fmaxf(mx, s[i]);
    mx = fmaxf(mx, __shfl_xor_sync(0xffffffffu, mx, 8));
    mx = fmaxf(mx, __shfl_xor_sync(0xffffffffu, mx, 16));

    float denom = 0.f;
    #pragma unroll
    for (int i = 0; i < 11; i++) {
        s[i] = __expf(s[i] - mx);
        denom += s[i];
    }
    denom += __shfl_xor_sync(0xffffffffu, denom, 8);
    denom += __shfl_xor_sync(0xffffffffu, denom, 16);

    float acc[8] = {0.f, 0.f, 0.f, 0.f, 0.f, 0.f, 0.f, 0.f};
    #pragma unroll
    for (int i = 0; i < 11; i++) {
        int o = i * 4 + g;
        int delta = c_offs[o];
        if (delta <= n) {
            uint4 vv = *(const uint4*)(vbase + (size_t)(n - delta) * DQG);
            float2 v0 = h2f2(vv.x), v1 = h2f2(vv.y), v2 = h2f2(vv.z), v3 = h2f2(vv.w);
            float w = s[i];
            acc[0] = fmaf(w, v0.x, acc[0]);
            acc[1] = fmaf(w, v0.y, acc[1]);
            acc[2] = fmaf(w, v1.x, acc[2]);
            acc[3] = fmaf(w, v1.y, acc[3]);
            acc[4] = fmaf(w, v2.x, acc[4]);
            acc[5] = fmaf(w, v2.y, acc[5]);
            acc[6] = fmaf(w, v3.x, acc[6]);
            acc[7] = fmaf(w, v3.y, acc[7]);
        }
    }
    #pragma unroll
    for (int d = 0; d < 8; d++) {
        acc[d] += __shfl_xor_sync(0xffffffffu, acc[d], 8);
        acc[d] += __shfl_xor_sync(0xffffffffu, acc[d], 16);
    }

    if (g == 0) {
        float inv = 1.0f / denom;
        uint4 gv = *(const uint4*)(gbase + (size_t)n * DQG);
        float2 g0 = h2f2(gv.x), g1 = h2f2(gv.y), g2 = h2f2(gv.z), g3 = h2f2(gv.w);
        __half2 o0 = __floats2half2_rn(acc[0] * inv * g0.x, acc[1] * inv * g0.y);
        __half2 o1 = __floats2half2_rn(acc[2] * inv * g1.x, acc[3] * inv * g1.y);
        __half2 o2 = __floats2half2_rn(acc[4] * inv * g2.x, acc[5] * inv * g2.y);
        __half2 o3 = __floats2half2_rn(acc[6] * inv * g3.x, acc[7] * inv * g3.y);
        uint4 ov;
        ov.x = *(uint32_t*)&o0; ov.y = *(uint32_t*)&o1;
        ov.z = *(uint32_t*)&o2; ov.w = *(uint32_t*)&o3;
        *(uint4*)(y + (size_t)n * DMODEL + h * HDIM + j * 8) = ov;
    }
}

// ---------------------------------------------------------------------------
// Launch
// ---------------------------------------------------------------------------
extern "C" void kernel_launch(void* const* d_in, const int* in_sizes, int n_in,
                              void* d_out, int out_size) {
    __half *s_xn, *s_qg, *s_y, *s_xn2, *s_h;
    float *s_x1, *s_bqg;
    __half *s_wqg, *s_wout, *s_wfc1, *s_wfc2;
    cudaGetSymbolAddress((void**)&s_xn,  g_xn);
    cudaGetSymbolAddress((void**)&s_qg,  g_qg);
    cudaGetSymbolAddress((void**)&s_y,   g_y);
    cudaGetSymbolAddress((void**)&s_x1,  g_x1);
    cudaGetSymbolAddress((void**)&s_xn2, g_xn2);
    cudaGetSymbolAddress((void**)&s_h,   g_h);
    cudaGetSymbolAddress((void**)&s_wqg, g_wqg);
    cudaGetSymbolAddress((void**)&s_wout,g_wout);
    cudaGetSymbolAddress((void**)&s_wfc1,g_wfc1);
    cudaGetSymbolAddress((void**)&s_wfc2,g_wfc2);
    cudaGetSymbolAddress((void**)&s_bqg, g_bqg);

    const float* x      = (const float*)d_in[0];
    const float* ln1_g  = (const float*)d_in[1];
    const float* ln1_b  = (const float*)d_in[2];
    const float* qkv_w  = (const float*)d_in[3];
    const float* qkv_b  = (const float*)d_in[4];
    const float* gate_w = (const float*)d_in[5];
    const float* gate_b = (const float*)d_in[6];
    const float* out_w  = (const float*)d_in[7];
    const float* out_b  = (const float*)d_in[8];
    const float* pbias  = (const float*)d_in[9];
    const float* ln2_g  = (const float*)d_in[10];
    const float* ln2_b  = (const float*)d_in[11];
    const float* fc1_w  = (const float*)d_in[12];
    const float* fc1_b  = (const float*)d_in[13];
    const float* fc2_w  = (const float*)d_in[14];
    const float* fc2_b  = (const float*)d_in[15];
    float* out = (float*)d_out;

    const int SM2   = 2 * (64 + 128) * 144;  // 55296 -> 4 CTAs/SM @256thr
    const int SM2_S = 2 * (64 + 64) * 144;   // 36864
    cudaFuncSetAttribute(hgemm<64,128,2,4,4,true >, cudaFuncAttributeMaxDynamicSharedMemorySize, SM2);
    cudaFuncSetAttribute(hgemm<64,128,2,4,3,true >, cudaFuncAttributeMaxDynamicSharedMemorySize, SM2);
    cudaFuncSetAttribute(hgemm<64,64,2,2,2,false >, cudaFuncAttributeMaxDynamicSharedMemorySize, SM2_S);
    cudaFuncSetAttribute(hgemm<64,64,2,4,2,false >, cudaFuncAttributeMaxDynamicSharedMemorySize, SM2_S);

    prep_kernel<<<6656, dim3(32, 8)>>>(qkv_w, gate_w, out_w, fc1_w, fc2_w);
    bias_cat<<<DQG / 256, 256>>>(qkv_b, gate_b);

    // 1) LN1 -> fp16
    ln_kernel<<<NSEQ, 256>>>(x, ln1_g, ln1_b, s_xn);
    // 2) [qkv|gate] = xn @ wqg + bqg (sigmoid on gate cols)
    hgemm<64,128,2,4,4,true><<<dim3(DQG / 128, NSEQ / 64), 256, SM2>>>(
        s_xn, s_wqg, s_bqg, nullptr, s_qg, DQG, DMODEL);
    // 3) attention (+gate)
    attn_kernel<<<(NSEQ * NHEAD) / 8, 256>>>(s_qg, pbias, s_y);
    // 4) x1 = x + y @ out_w + out_b  (R9 shape: 512 CTAs, 128 thr)
    hgemm<64,64,2,2,2,false><<<dim3(DMODEL / 64, NSEQ / 64), 128, SM2_S>>>(
        s_y, s_wout, out_b, x, s_x1, DMODEL, DMODEL);
    // 5) LN2 -> fp16
    ln_kernel<<<NSEQ, 256>>>(s_x1, ln2_g, ln2_b, s_xn2);
    // 6) h = gelu(xn2 @ fc1_w + fc1_b)
    hgemm<64,128,2,4,3,true><<<dim3(DFF / 128, NSEQ / 64), 256, SM2>>>(
        s_xn2, s_wfc1, fc1_b, nullptr, s_h, DFF, DMODEL);
    // 7) out = x1 + h @ fc2_w + fc2_b  (512 CTAs, 8 warps, ~3.5 CTAs/SM)
    hgemm<64,64,2,4,2,false><<<dim3(DMODEL / 64, NSEQ / 64), 256, SM2_S>>>(
        s_h, s_wfc2, fc2_b, s_x1, out, DMODEL, DFF);
}

// round 15
// speedup vs baseline: 1.0268x; 1.0268x over previous
#include <cuda_runtime.h>
#include <cuda_fp16.h>
#include <math.h>
#include <stdint.h>

// ---------------------------------------------------------------------------
#define NSEQ 2048
#define DMODEL 1024
#define NHEAD 16
#define HDIM 64
#define DFF 4096
#define NOFF 44
#define D3 (3 * DMODEL)
#define DQG 4096          // qkv + gate combined width

__constant__ int c_offs[NOFF] = {
    0,1,2,3,4,5,6,7,8,9,10,11,12,13,14,15,16,17,18,19,20,21,22,23,24,25,26,27,
    28,29,30,31,32,48,64,96,128,192,256,384,512,768,1024,1536};

// ---------------------------------------------------------------------------
// Scratch
// ---------------------------------------------------------------------------
__device__ __half g_xn [NSEQ * DMODEL];
__device__ __half g_qg [NSEQ * DQG];      // [q|k|v|gate] fp16
__device__ __half g_y  [NSEQ * DMODEL];
__device__ float  g_x1 [NSEQ * DMODEL];
__device__ __half g_xn2[NSEQ * DMODEL];
__device__ __half g_h  [NSEQ * DFF];
__device__ float  g_part[2][NSEQ * DMODEL];  // fc2 split-K partials
__device__ __half g_wqg [DQG * DMODEL];
__device__ __half g_wout[DMODEL * DMODEL];
__device__ __half g_wfc1[DFF * DMODEL];
__device__ __half g_wfc2[DMODEL * DFF];
__device__ float  g_bqg [DQG];

// ---------------------------------------------------------------------------
__device__ __forceinline__ uint32_t smem_u32(const void* p) {
    uint32_t a;
    asm("{ .reg .u64 t; cvta.to.shared.u64 t, %1; cvt.u32.u64 %0, t; }"
        : "=r"(a) : "l"(p));
    return a;
}

#define CPA16(dst, src) \
    asm volatile("cp.async.cg.shared.global [%0], [%1], 16;\n" :: "r"(dst), "l"(src))

#define LDSM_X4(r0, r1, r2, r3, addr) \
    asm volatile("ldmatrix.sync.aligned.m8n8.x4.shared.b16 {%0,%1,%2,%3}, [%4];" \
        : "=r"(r0), "=r"(r1), "=r"(r2), "=r"(r3) : "r"(addr))

__device__ __forceinline__ float2 h2f2(uint32_t u) {
    __half2 h = *(__half2*)&u;
    return __half22float2(h);
}

// ---------------------------------------------------------------------------
// Fused weight prep (R9 version): 32x32 tiles, [K,N]fp32 -> [N,K]fp16
// ---------------------------------------------------------------------------
__global__ void prep_kernel(const float* __restrict__ qkv_w,
                            const float* __restrict__ gate_w,
                            const float* __restrict__ out_w,
                            const float* __restrict__ fc1_w,
                            const float* __restrict__ fc2_w) {
    __shared__ float t[32][33];
    int bid = blockIdx.x;
    const float* W; __half* Wt; int K, Nw, b;
    if (bid < 3072)       { b = bid;        W = qkv_w;  Wt = g_wqg;                       K = 1024; Nw = 3072; }
    else if (bid < 4096)  { b = bid - 3072; W = gate_w; Wt = g_wqg + (size_t)3072 * 1024; K = 1024; Nw = 1024; }
    else if (bid < 5120)  { b = bid - 4096; W = out_w;  Wt = g_wout;                      K = 1024; Nw = 1024; }
    else if (bid < 9216)  { b = bid - 5120; W = fc1_w;  Wt = g_wfc1;                      K = 1024; Nw = 4096; }
    else                  { b = bid - 9216; W = fc2_w;  Wt = g_wfc2;                      K = 4096; Nw = 1024; }
    int nx = Nw >> 5;
    int n0 = (b % nx) * 32, k0 = (b / nx) * 32;
    int tx = threadIdx.x, ty = threadIdx.y;
    #pragma unroll
    for (int i = 0; i < 32; i += 8)
        t[ty + i][tx] = W[(size_t)(k0 + ty + i) * Nw + n0 + tx];
    __syncthreads();
    #pragma unroll
    for (int i = 0; i < 32; i += 8)
        Wt[(size_t)(n0 + ty + i) * K + k0 + tx] = __float2half_rn(t[tx][ty + i]);
}

__global__ void bias_cat(const float* __restrict__ qkv_b,
                         const float* __restrict__ gate_b) {
    int i = blockIdx.x * 256 + threadIdx.x;
    if (i < DQG) g_bqg[i] = (i < D3) ? qkv_b[i] : gate_b[i - D3];
}

// ---------------------------------------------------------------------------
// LayerNorm -> fp16
// ---------------------------------------------------------------------------
__global__ void ln_kernel(const float* __restrict__ x,
                          const float* __restrict__ g,
                          const float* __restrict__ b,
                          __half* __restrict__ out) {
    int row = blockIdx.x;
    int tid = threadIdx.x;
    const float4* xr = (const float4*)(x + (size_t)row * DMODEL);
    float4 v = xr[tid];
    float s  = v.x + v.y + v.z + v.w;
    float sq = v.x * v.x + v.y * v.y + v.z * v.z + v.w * v.w;
    #pragma unroll
    for (int o = 16; o > 0; o >>= 1) {
        s  += __shfl_xor_sync(0xffffffffu, s,  o);
        sq += __shfl_xor_sync(0xffffffffu, sq, o);
    }
    __shared__ float sh[16];
    int wid = tid >> 5, lane = tid & 31;
    if (lane == 0) { sh[wid] = s; sh[wid + 8] = sq; }
    __syncthreads();
    float ts = 0.f, tq = 0.f;
    #pragma unroll
    for (int w = 0; w < 8; w++) { ts += sh[w]; tq += sh[w + 8]; }
    float mu  = ts * (1.0f / DMODEL);
    float var = tq * (1.0f / DMODEL) - mu * mu;
    var = var > 0.f ? var : 0.f;
    float rstd = rsqrtf(var + 1e-5f);

    float4 gv = ((const float4*)g)[tid];
    float4 bv = ((const float4*)b)[tid];
    __half2 h0 = __floats2half2_rn((v.x - mu) * rstd * gv.x + bv.x,
                                   (v.y - mu) * rstd * gv.y + bv.y);
    __half2 h1 = __floats2half2_rn((v.z - mu) * rstd * gv.z + bv.z,
                                   (v.w - mu) * rstd * gv.w + bv.w);
    uint2 o;
    o.x = *(uint32_t*)&h0;
    o.y = *(uint32_t*)&h1;
    *(uint2*)(out + (size_t)row * DMODEL + tid * 4) = o;
}

// ---------------------------------------------------------------------------
// fp16 tile loader: ROWS x 64 halves, row stride 144B
// ---------------------------------------------------------------------------
template <int ROWS, int NT>
__device__ __forceinline__ void tile_load(uint32_t dst, const __half* src,
                                          int ldK, int tid) {
    #pragma unroll
    for (int i = 0; i < ROWS * 8 / NT; i++) {
        int c = i * NT + tid;
        int m = c >> 3, q = c & 7;
        CPA16(dst + (uint32_t)(m * 144 + q * 16), src + (size_t)m * ldK + q * 8);
    }
}

// ---------------------------------------------------------------------------
// fp16 GEMM (R9-exact): warp tile 32x32, 8 warps, 2-stage cp.async.
//   EPI 2: +bias+res(fp32)->fp32 | 3: gelu->fp16 | 4: qkv|gate mixed ->fp16
// ---------------------------------------------------------------------------
template <int BM, int BN, int WM, int WN, int EPI, bool OUTH>
__global__ void __launch_bounds__(WM * WN * 32, 4)
hgemm(const __half* __restrict__ A, const __half* __restrict__ Bt,
      const float* __restrict__ bias, const float* __restrict__ res,
      void* __restrict__ Cv, int N, int K) {
    constexpr int NT = WM * WN * 32;
    constexpr int MI = BM / WM / 16;
    constexpr int NI = BN / WN / 8;
    constexpr int NJ = NI / 2;
    constexpr uint32_t ASTAGE = BM * 144;
    constexpr uint32_t BSTAGE = BN * 144;

    extern __shared__ char dsm[];

    const int tid  = threadIdx.x;
    const int warp = tid >> 5, lane = tid & 31;
    const int g    = lane >> 2, t4 = lane & 3;
    const int warpM = (warp / WN) * (BM / WM);
    const int warpN = (warp % WN) * (BN / WN);
    const int rowBase = blockIdx.y * BM;
    const int colBase = blockIdx.x * BN;

    const uint32_t smA = smem_u32(dsm);
    const uint32_t smB = smA + 2 * ASTAGE;
    const uint32_t aLds = smA + (uint32_t)((warpM + (lane & 15)) * 144 + (lane >> 4) * 16);
    const uint32_t bLds = smB + (uint32_t)((warpN + (lane & 15)) * 144 + (lane >> 4) * 16);

    const __half* Ag = A + (size_t)rowBase * K;
    const __half* Bg = Bt + (size_t)colBase * K;

    float acc[MI][NI][4];
    #pragma unroll
    for (int mi = 0; mi < MI; mi++)
        #pragma unroll
        for (int ni = 0; ni < NI; ni++)
            #pragma unroll
            for (int r = 0; r < 4; r++) acc[mi][ni][r] = 0.f;

    const int KT = K / 64;
    tile_load<BM, NT>(smA, Ag, K, tid);
    tile_load<BN, NT>(smB, Bg, K, tid);
    asm volatile("cp.async.commit_group;\n");

    for (int kt = 0; kt < KT; kt++) {
        asm volatile("cp.async.wait_group 0;\n");
        __syncthreads();

        if (kt + 1 < KT) {
            const uint32_t nb = (uint32_t)((kt + 1) & 1);
            tile_load<BM, NT>(smA + nb * ASTAGE, Ag + (kt + 1) * 64, K, tid);
            tile_load<BN, NT>(smB + nb * BSTAGE, Bg + (kt + 1) * 64, K, tid);
            asm volatile("cp.async.commit_group;\n");
        }

        const uint32_t aOff = aLds + (uint32_t)(kt & 1) * ASTAGE;
        const uint32_t bOff = bLds + (uint32_t)(kt & 1) * BSTAGE;
        #pragma unroll
        for (int ks = 0; ks < 4; ks++) {
            uint32_t af[MI][4], bf[NJ][4];
            #pragma unroll
            for (int mi = 0; mi < MI; mi++)
                LDSM_X4(af[mi][0], af[mi][1], af[mi][2], af[mi][3],
                        aOff + (uint32_t)(mi * 16 * 144 + ks * 32));
            #pragma unroll
            for (int nj = 0; nj < NJ; nj++)
                LDSM_X4(bf[nj][0], bf[nj][1], bf[nj][2], bf[nj][3],
                        bOff + (uint32_t)(nj * 16 * 144 + ks * 32));
            #pragma unroll
            for (int mi = 0; mi < MI; mi++)
                #pragma unroll
                for (int nj = 0; nj < NJ; nj++) {
                    asm volatile(
                        "mma.sync.aligned.m16n8k16.row.col.f32.f16.f16.f32 "
                        "{%0,%1,%2,%3}, {%4,%5,%6,%7}, {%8,%9}, {%0,%1,%2,%3};\n"
                        : "+f"(acc[mi][2*nj][0]), "+f"(acc[mi][2*nj][1]),
                          "+f"(acc[mi][2*nj][2]), "+f"(acc[mi][2*nj][3])
                        : "r"(af[mi][0]), "r"(af[mi][1]), "r"(af[mi][2]), "r"(af[mi][3]),
                          "r"(bf[nj][0]), "r"(bf[nj][2]));
                    asm volatile(
                        "mma.sync.aligned.m16n8k16.row.col.f32.f16.f16.f32 "
                        "{%0,%1,%2,%3}, {%4,%5,%6,%7}, {%8,%9}, {%0,%1,%2,%3};\n"
                        : "+f"(acc[mi][2*nj+1][0]), "+f"(acc[mi][2*nj+1][1]),
                          "+f"(acc[mi][2*nj+1][2]), "+f"(acc[mi][2*nj+1][3])
                        : "r"(af[mi][0]), "r"(af[mi][1]), "r"(af[mi][2]), "r"(af[mi][3]),
                          "r"(bf[nj][1]), "r"(bf[nj][3]));
                }
        }
        __syncthreads();
    }

    const bool sig = (EPI == 4) && (colBase >= D3);
    #pragma unroll
    for (int mi = 0; mi < MI; mi++) {
        #pragma unroll
        for (int ni = 0; ni < NI; ni++) {
            int row = rowBase + warpM + mi * 16 + g;
            int col = colBase + warpN + ni * 8 + t4 * 2;
            float b0 = bias[col], b1 = bias[col + 1];
            #pragma unroll
            for (int hh = 0; hh < 2; hh++) {
                int r = row + hh * 8;
                float vx = acc[mi][ni][hh * 2 + 0] + b0;
                float vy = acc[mi][ni][hh * 2 + 1] + b1;
                if (EPI == 3) {
                    vx = 0.5f * vx * (1.0f + erff(vx * 0.70710678118654752f));
                    vy = 0.5f * vy * (1.0f + erff(vy * 0.70710678118654752f));
                } else if (EPI == 4) {
                    if (sig) {
                        vx = 1.0f / (1.0f + __expf(-vx));
                        vy = 1.0f / (1.0f + __expf(-vy));
                    }
                }
                size_t off = (size_t)r * N + col;
                if (EPI == 2) {
                    float2 rr = *(const float2*)(res + off);
                    vx += rr.x; vy += rr.y;
                }
                if (OUTH) {
                    __half2 hv = __floats2half2_rn(vx, vy);
                    *(__half2*)((__half*)Cv + off) = hv;
                } else {
                    *(float2*)((float*)Cv + off) = make_float2(vx, vy);
                }
            }
        }
    }
}

// ---------------------------------------------------------------------------
// fc2 split-K GEMM: grid (8, 32, 2); z selects K-half; raw fp32 partials.
// Same mainloop as hgemm (BM=64, BN=128, 8 warps).
// ---------------------------------------------------------------------------
__global__ void __launch_bounds__(256, 4)
hgemm_sk(const __half* __restrict__ A, const __half* __restrict__ Bt) {
    constexpr int BM = 64, BN = 128, WN = 4;
    constexpr int NT = 256, MI = 2, NI = 4, NJ = 2;
    constexpr int LD = DFF;           // row stride of A and Bt (K total)
    constexpr int KLEN = DFF / 2;     // K per split
    constexpr uint32_t ASTAGE = BM * 144;
    constexpr uint32_t BSTAGE = BN * 144;

    extern __shared__ char dsm[];

    const int tid  = threadIdx.x;
    const int warp = tid >> 5, lane = tid & 31;
    const int g    = lane >> 2, t4 = lane & 3;
    const int warpM = (warp / WN) * 32;
    const int warpN = (warp % WN) * 32;
    const int rowBase = blockIdx.y * BM;
    const int colBase = blockIdx.x * BN;
    const int z = blockIdx.z;

    const uint32_t smA = smem_u32(dsm);
    const uint32_t smB = smA + 2 * ASTAGE;
    const uint32_t aLds = smA + (uint32_t)((warpM + (lane & 15)) * 144 + (lane >> 4) * 16);
    const uint32_t bLds = smB + (uint32_t)((warpN + (lane & 15)) * 144 + (lane >> 4) * 16);

    const __half* Ag = A + (size_t)rowBase * LD + z * KLEN;
    const __half* Bg = Bt + (size_t)colBase * LD + z * KLEN;
    float* Cp = g_part[z];

    float acc[MI][NI][4];
    #pragma unroll
    for (int mi = 0; mi < MI; mi++)
        #pragma unroll
        for (int ni = 0; ni < NI; ni++)
            #pragma unroll
            for (int r = 0; r < 4; r++) acc[mi][ni][r] = 0.f;

    const int KT = KLEN / 64;
    tile_load<BM, NT>(smA, Ag, LD, tid);
    tile_load<BN, NT>(smB, Bg, LD, tid);
    asm volatile("cp.async.commit_group;\n");

    for (int kt = 0; kt < KT; kt++) {
        asm volatile("cp.async.wait_group 0;\n");
        __syncthreads();

        if (kt + 1 < KT) {
            const uint32_t nb = (uint32_t)((kt + 1) & 1);
            tile_load<BM, NT>(smA + nb * ASTAGE, Ag + (kt + 1) * 64, LD, tid);
            tile_load<BN, NT>(smB + nb * BSTAGE, Bg + (kt + 1) * 64, LD, tid);
            asm volatile("cp.async.commit_group;\n");
        }

        const uint32_t aOff = aLds + (uint32_t)(kt & 1) * ASTAGE;
        const uint32_t bOff = bLds + (uint32_t)(kt & 1) * BSTAGE;
        #pragma unroll
        for (int ks = 0; ks < 4; ks++) {
            uint32_t af[MI][4], bf[NJ][4];
            #pragma unroll
            for (int mi = 0; mi < MI; mi++)
                LDSM_X4(af[mi][0], af[mi][1], af[mi][2], af[mi][3],
                        aOff + (uint32_t)(mi * 16 * 144 + ks * 32));
            #pragma unroll
            for (int nj = 0; nj < NJ; nj++)
                LDSM_X4(bf[nj][0], bf[nj][1], bf[nj][2], bf[nj][3],
                        bOff + (uint32_t)(nj * 16 * 144 + ks * 32));
            #pragma unroll
            for (int mi = 0; mi < MI; mi++)
                #pragma unroll
                for (int nj = 0; nj < NJ; nj++) {
                    asm volatile(
                        "mma.sync.aligned.m16n8k16.row.col.f32.f16.f16.f32 "
                        "{%0,%1,%2,%3}, {%4,%5,%6,%7}, {%8,%9}, {%0,%1,%2,%3};\n"
                        : "+f"(acc[mi][2*nj][0]), "+f"(acc[mi][2*nj][1]),
                          "+f"(acc[mi][2*nj][2]), "+f"(acc[mi][2*nj][3])
                        : "r"(af[mi][0]), "r"(af[mi][1]), "r"(af[mi][2]), "r"(af[mi][3]),
                          "r"(bf[nj][0]), "r"(bf[nj][2]));
                    asm volatile(
                        "mma.sync.aligned.m16n8k16.row.col.f32.f16.f16.f32 "
                        "{%0,%1,%2,%3}, {%4,%5,%6,%7}, {%8,%9}, {%0,%1,%2,%3};\n"
                        : "+f"(acc[mi][2*nj+1][0]), "+f"(acc[mi][2*nj+1][1]),
                          "+f"(acc[mi][2*nj+1][2]), "+f"(acc[mi][2*nj+1][3])
                        : "r"(af[mi][0]), "r"(af[mi][1]), "r"(af[mi][2]), "r"(af[mi][3]),
                          "r"(bf[nj][1]), "r"(bf[nj][3]));
                }
        }
        __syncthreads();
    }

    #pragma unroll
    for (int mi = 0; mi < MI; mi++) {
        #pragma unroll
        for (int ni = 0; ni < NI; ni++) {
            int row = rowBase + warpM + mi * 16 + g;
            int col = colBase + warpN + ni * 8 + t4 * 2;
            #pragma unroll
            for (int hh = 0; hh < 2; hh++) {
                int r = row + hh * 8;
                *(float2*)(Cp + (size_t)r * DMODEL + col) =
                    make_float2(acc[mi][ni][hh * 2 + 0], acc[mi][ni][hh * 2 + 1]);
            }
        }
    }
}

// combine: out = x1 + bias + p0 + p1   (float4, deterministic order)
__global__ void combine_kernel(const float* __restrict__ x1,
                               const float* __restrict__ bias,
                               float* __restrict__ out) {
    int i = blockIdx.x * 256 + threadIdx.x;         // float4 index
    int col = (i * 4) & (DMODEL - 1);
    const float* p0 = g_part[0];
    const float* p1 = g_part[1];
    float4 a = ((const float4*)x1)[i];
    float4 b = ((const float4*)p0)[i];
    float4 c = ((const float4*)p1)[i];
    float4 o;
    o.x = a.x + bias[col + 0] + (b.x + c.x);
    o.y = a.y + bias[col + 1] + (b.y + c.y);
    o.z = a.z + bias[col + 2] + (b.z + c.z);
    o.w = a.w + bias[col + 3] + (b.w + c.w);
    ((float4*)out)[i] = o;
}

// ---------------------------------------------------------------------------
// Offset attention on combined [q|k|v|gate] buffer (stride DQG).
// ---------------------------------------------------------------------------
__global__ void attn_kernel(const __half* __restrict__ qg,
                            const float* __restrict__ pos_bias,
                            __half* __restrict__ y) {
    int warp = blockIdx.x * (blockDim.x >> 5) + (threadIdx.x >> 5);
    int lane = threadIdx.x & 31;
    int h = warp >> 11;
    int n = warp & 2047;
    int j = lane & 7;
    int g = lane >> 3;

    const __half* qrow  = qg + (size_t)n * DQG + h * HDIM + j * 8;
    const __half* kbase = qg + DMODEL + h * HDIM + j * 8;
    const __half* vbase = qg + 2 * DMODEL + h * HDIM + j * 8;
    const __half* gbase = qg + 3 * DMODEL + h * HDIM + j * 8;

    uint4 qv = *(const uint4*)(qrow);
    float2 q0 = h2f2(qv.x), q1 = h2f2(qv.y), q2 = h2f2(qv.z), q3 = h2f2(qv.w);

    const float scale = 0.125f;
    float s[11];

    #pragma unroll
    for (int i = 0; i < 11; i++) {
        int o = i * 4 + g;
        int delta = c_offs[o];
        bool valid = (delta <= n);
        float p = 0.f;
        if (valid) {
            uint4 kv = *(const uint4*)(kbase + (size_t)(n - delta) * DQG);
            float2 k0 = h2f2(kv.x), k1 = h2f2(kv.y), k2 = h2f2(kv.z), k3 = h2f2(kv.w);
            p = q0.x * k0.x + q0.y * k0.y + q1.x * k1.x + q1.y * k1.y
              + q2.x * k2.x + q2.y * k2.y + q3.x * k3.x + q3.y * k3.y;
        }
        p += __shfl_xor_sync(0xffffffffu, p, 1);
        p += __shfl_xor_sync(0xffffffffu, p, 2);
        p += __shfl_xor_sync(0xffffffffu, p, 4);
        s[i] = valid ? p * scale + pos_bias[o * NHEAD + h] : -INFINITY;
    }

    float mx = s[0];
    #pragma unroll
    for (int i = 1; i < 11; i++) mx = fmaxf(mx, s[i]);
    mx = fmaxf(mx, __shfl_xor_sync(0xffffffffu, mx, 8));
    mx = fmaxf(mx, __shfl_xor_sync(0xffffffffu, mx, 16));

    float denom = 0.f;
    #pragma unroll
    for (int i = 0; i < 11; i++) {
        s[i] = __expf(s[i] - mx);
        denom += s[i];
    }
    denom += __shfl_xor_sync(0xffffffffu, denom, 8);
    denom += __shfl_xor_sync(0xffffffffu, denom, 16);

    float acc[8] = {0.f, 0.f, 0.f, 0.f, 0.f, 0.f, 0.f, 0.f};
    #pragma unroll
    for (int i = 0; i < 11; i++) {
        int o = i * 4 + g;
        int delta = c_offs[o];
        if (delta <= n) {
            uint4 vv = *(const uint4*)(vbase + (size_t)(n - delta) * DQG);
            float2 v0 = h2f2(vv.x), v1 = h2f2(vv.y), v2 = h2f2(vv.z), v3 = h2f2(vv.w);
            float w = s[i];
            acc[0] = fmaf(w, v0.x, acc[0]);
            acc[1] = fmaf(w, v0.y, acc[1]);
            acc[2] = fmaf(w, v1.x, acc[2]);
            acc[3] = fmaf(w, v1.y, acc[3]);
            acc[4] = fmaf(w, v2.x, acc[4]);
            acc[5] = fmaf(w, v2.y, acc[5]);
            acc[6] = fmaf(w, v3.x, acc[6]);
            acc[7] = fmaf(w, v3.y, acc[7]);
        }
    }
    #pragma unroll
    for (int d = 0; d < 8; d++) {
        acc[d] += __shfl_xor_sync(0xffffffffu, acc[d], 8);
        acc[d] += __shfl_xor_sync(0xffffffffu, acc[d], 16);
    }

    if (g == 0) {
        float inv = 1.0f / denom;
        uint4 gv = *(const uint4*)(gbase + (size_t)n * DQG);
        float2 g0 = h2f2(gv.x), g1 = h2f2(gv.y), g2 = h2f2(gv.z), g3 = h2f2(gv.w);
        __half2 o0 = __floats2half2_rn(acc[0] * inv * g0.x, acc[1] * inv * g0.y);
        __half2 o1 = __floats2half2_rn(acc[2] * inv * g1.x, acc[3] * inv * g1.y);
        __half2 o2 = __floats2half2_rn(acc[4] * inv * g2.x, acc[5] * inv * g2.y);
        __half2 o3 = __floats2half2_rn(acc[6] * inv * g3.x, acc[7] * inv * g3.y);
        uint4 ov;
        ov.x = *(uint32_t*)&o0; ov.y = *(uint32_t*)&o1;
        ov.z = *(uint32_t*)&o2; ov.w = *(uint32_t*)&o3;
        *(uint4*)(y + (size_t)n * DMODEL + h * HDIM + j * 8) = ov;
    }
}

// ---------------------------------------------------------------------------
// Launch
// ---------------------------------------------------------------------------
extern "C" void kernel_launch(void* const* d_in, const int* in_sizes, int n_in,
                              void* d_out, int out_size) {
    __half *s_xn, *s_qg, *s_y, *s_xn2, *s_h;
    float *s_x1, *s_bqg;
    __half *s_wqg, *s_wout, *s_wfc1, *s_wfc2;
    cudaGetSymbolAddress((void**)&s_xn,  g_xn);
    cudaGetSymbolAddress((void**)&s_qg,  g_qg);
    cudaGetSymbolAddress((void**)&s_y,   g_y);
    cudaGetSymbolAddress((void**)&s_x1,  g_x1);
    cudaGetSymbolAddress((void**)&s_xn2, g_xn2);
    cudaGetSymbolAddress((void**)&s_h,   g_h);
    cudaGetSymbolAddress((void**)&s_wqg, g_wqg);
    cudaGetSymbolAddress((void**)&s_wout,g_wout);
    cudaGetSymbolAddress((void**)&s_wfc1,g_wfc1);
    cudaGetSymbolAddress((void**)&s_wfc2,g_wfc2);
    cudaGetSymbolAddress((void**)&s_bqg, g_bqg);

    const float* x      = (const float*)d_in[0];
    const float* ln1_g  = (const float*)d_in[1];
    const float* ln1_b  = (const float*)d_in[2];
    const float* qkv_w  = (const float*)d_in[3];
    const float* qkv_b  = (const float*)d_in[4];
    const float* gate_w = (const float*)d_in[5];
    const float* gate_b = (const float*)d_in[6];
    const float* out_w  = (const float*)d_in[7];
    const float* out_b  = (const float*)d_in[8];
    const float* pbias  = (const float*)d_in[9];
    const float* ln2_g  = (const float*)d_in[10];
    const float* ln2_b  = (const float*)d_in[11];
    const float* fc1_w  = (const float*)d_in[12];
    const float* fc1_b  = (const float*)d_in[13];
    const float* fc2_w  = (const float*)d_in[14];
    const float* fc2_b  = (const float*)d_in[15];
    float* out = (float*)d_out;

    const int SM2 = 2 * (64 + 128) * 144;  // 55296 -> 4 CTAs/SM @256thr
    cudaFuncSetAttribute(hgemm<64,128,2,4,4,true >, cudaFuncAttributeMaxDynamicSharedMemorySize, SM2);
    cudaFuncSetAttribute(hgemm<64,128,2,4,3,true >, cudaFuncAttributeMaxDynamicSharedMemorySize, SM2);
    cudaFuncSetAttribute(hgemm<64,128,2,4,2,false>, cudaFuncAttributeMaxDynamicSharedMemorySize, SM2);
    cudaFuncSetAttribute(hgemm_sk, cudaFuncAttributeMaxDynamicSharedMemorySize, SM2);

    prep_kernel<<<13312, dim3(32, 8)>>>(qkv_w, gate_w, out_w, fc1_w, fc2_w);
    bias_cat<<<DQG / 256, 256>>>(qkv_b, gate_b);

    // 1) LN1 -> fp16
    ln_kernel<<<NSEQ, 256>>>(x, ln1_g, ln1_b, s_xn);
    // 2) [qkv|gate] = xn @ wqg + bqg (sigmoid on gate cols)
    hgemm<64,128,2,4,4,true><<<dim3(DQG / 128, NSEQ / 64), 256, SM2>>>(
        s_xn, s_wqg, s_bqg, nullptr, s_qg, DQG, DMODEL);
    // 3) attention (+gate)
    attn_kernel<<<(NSEQ * NHEAD) / 8, 256>>>(s_qg, pbias, s_y);
    // 4) x1 = x + y @ out_w + out_b
    hgemm<64,128,2,4,2,false><<<dim3(DMODEL / 128, NSEQ / 64), 256, SM2>>>(
        s_y, s_wout, out_b, x, s_x1, DMODEL, DMODEL);
    // 5) LN2 -> fp16
    ln_kernel<<<NSEQ, 256>>>(s_x1, ln2_g, ln2_b, s_xn2);
    // 6) h = gelu(xn2 @ fc1_w + fc1_b)
    hgemm<64,128,2,4,3,true><<<dim3(DFF / 128, NSEQ / 64), 256, SM2>>>(
        s_xn2, s_wfc1, fc1_b, nullptr, s_h, DFF, DMODEL);
    // 7a) fc2 split-K partials: 512 CTAs in one launch
    hgemm_sk<<<dim3(DMODEL / 128, NSEQ / 64, 2), 256, SM2>>>(s_h, s_wfc2);
    // 7b) out = x1 + fc2_b + p0 + p1
    combine_kernel<<<NSEQ * DMODEL / 4 / 256, 256>>>(s_x1, fc2_b, out);
}

// round 17
// speedup vs baseline: 1.0477x; 1.0204x over previous
#include <cuda_runtime.h>
#include <cuda_fp16.h>
#include <math.h>
#include <stdint.h>

// ---------------------------------------------------------------------------
#define NSEQ 2048
#define DMODEL 1024
#define NHEAD 16
#define HDIM 64
#define DFF 4096
#define NOFF 44
#define D3 (3 * DMODEL)
#define DQG 4096          // qkv + gate combined width

__constant__ int c_offs[NOFF] = {
    0,1,2,3,4,5,6,7,8,9,10,11,12,13,14,15,16,17,18,19,20,21,22,23,24,25,26,27,
    28,29,30,31,32,48,64,96,128,192,256,384,512,768,1024,1536};

// ---------------------------------------------------------------------------
// Scratch
// ---------------------------------------------------------------------------
__device__ __half g_xn [NSEQ * DMODEL];
__device__ __half g_qg [NSEQ * DQG];      // [q|k|v|gate] fp16
__device__ __half g_y  [NSEQ * DMODEL];
__device__ float  g_x1 [NSEQ * DMODEL];
__device__ __half g_xn2[NSEQ * DMODEL];
__device__ __half g_h  [NSEQ * DFF];
__device__ float  g_part[2][NSEQ * DMODEL];  // fc2 split-K partials
__device__ __half g_wqg [DQG * DMODEL];
__device__ __half g_wout[DMODEL * DMODEL];
__device__ __half g_wfc1[DFF * DMODEL];
__device__ __half g_wfc2[DMODEL * DFF];
__device__ float  g_bqg [DQG];

// ---------------------------------------------------------------------------
__device__ __forceinline__ uint32_t smem_u32(const void* p) {
    uint32_t a;
    asm("{ .reg .u64 t; cvta.to.shared.u64 t, %1; cvt.u32.u64 %0, t; }"
        : "=r"(a) : "l"(p));
    return a;
}

#define CPA16(dst, src) \
    asm volatile("cp.async.cg.shared.global [%0], [%1], 16;\n" :: "r"(dst), "l"(src))

#define LDSM_X4(r0, r1, r2, r3, addr) \
    asm volatile("ldmatrix.sync.aligned.m8n8.x4.shared.b16 {%0,%1,%2,%3}, [%4];" \
        : "=r"(r0), "=r"(r1), "=r"(r2), "=r"(r3) : "r"(addr))

__device__ __forceinline__ float2 h2f2(uint32_t u) {
    __half2 h = *(__half2*)&u;
    return __half22float2(h);
}

// ---------------------------------------------------------------------------
// Weight prep (half2 writes): [K,N]fp32 -> [N,K]fp16, 64k x 32n tiles.
// Reads 128B rows, writes 4B half2 per lane (64B/warp-row, coalesced).
// blocks: qkv 1536 | gate 512 | out 512 | fc1 2048 | fc2 2048 = 6656
// ---------------------------------------------------------------------------
__global__ void prep_kernel(const float* __restrict__ qkv_w,
                            const float* __restrict__ gate_w,
                            const float* __restrict__ out_w,
                            const float* __restrict__ fc1_w,
                            const float* __restrict__ fc2_w) {
    __shared__ float t[64][33];
    int bid = blockIdx.x;
    const float* W; __half* Wt; int K, Nw, b;
    if (bid < 1536)       { b = bid;        W = qkv_w;  Wt = g_wqg;                       K = 1024; Nw = 3072; }
    else if (bid < 2048)  { b = bid - 1536; W = gate_w; Wt = g_wqg + (size_t)3072 * 1024; K = 1024; Nw = 1024; }
    else if (bid < 2560)  { b = bid - 2048; W = out_w;  Wt = g_wout;                      K = 1024; Nw = 1024; }
    else if (bid < 4608)  { b = bid - 2560; W = fc1_w;  Wt = g_wfc1;                      K = 1024; Nw = 4096; }
    else                  { b = bid - 4608; W = fc2_w;  Wt = g_wfc2;                      K = 4096; Nw = 1024; }
    int nx = Nw >> 5;
    int n0 = (b % nx) * 32, k0 = (b / nx) * 64;
    int tx = threadIdx.x, ty = threadIdx.y;   // (32, 8)
    #pragma unroll
    for (int i = 0; i < 8; i++) {
        int kr = ty + i * 8;
        t[kr][tx] = W[(size_t)(k0 + kr) * Nw + n0 + tx];
    }
    __syncthreads();
    #pragma unroll
    for (int i = 0; i < 4; i++) {
        int nr = ty + i * 8;
        __half2 hv = __floats2half2_rn(t[tx * 2][nr], t[tx * 2 + 1][nr]);
        *(__half2*)(Wt + (size_t)(n0 + nr) * K + k0 + tx * 2) = hv;
    }
}

__global__ void bias_cat(const float* __restrict__ qkv_b,
                         const float* __restrict__ gate_b) {
    int i = blockIdx.x * 256 + threadIdx.x;
    if (i < DQG) g_bqg[i] = (i < D3) ? qkv_b[i] : gate_b[i - D3];
}

// ---------------------------------------------------------------------------
// LayerNorm -> fp16
// ---------------------------------------------------------------------------
__global__ void ln_kernel(const float* __restrict__ x,
                          const float* __restrict__ g,
                          const float* __restrict__ b,
                          __half* __restrict__ out) {
    int row = blockIdx.x;
    int tid = threadIdx.x;
    const float4* xr = (const float4*)(x + (size_t)row * DMODEL);
    float4 v = xr[tid];
    float s  = v.x + v.y + v.z + v.w;
    float sq = v.x * v.x + v.y * v.y + v.z * v.z + v.w * v.w;
    #pragma unroll
    for (int o = 16; o > 0; o >>= 1) {
        s  += __shfl_xor_sync(0xffffffffu, s,  o);
        sq += __shfl_xor_sync(0xffffffffu, sq, o);
    }
    __shared__ float sh[16];
    int wid = tid >> 5, lane = tid & 31;
    if (lane == 0) { sh[wid] = s; sh[wid + 8] = sq; }
    __syncthreads();
    float ts = 0.f, tq = 0.f;
    #pragma unroll
    for (int w = 0; w < 8; w++) { ts += sh[w]; tq += sh[w + 8]; }
    float mu  = ts * (1.0f / DMODEL);
    float var = tq * (1.0f / DMODEL) - mu * mu;
    var = var > 0.f ? var : 0.f;
    float rstd = rsqrtf(var + 1e-5f);

    float4 gv = ((const float4*)g)[tid];
    float4 bv = ((const float4*)b)[tid];
    __half2 h0 = __floats2half2_rn((v.x - mu) * rstd * gv.x + bv.x,
                                   (v.y - mu) * rstd * gv.y + bv.y);
    __half2 h1 = __floats2half2_rn((v.z - mu) * rstd * gv.z + bv.z,
                                   (v.w - mu) * rstd * gv.w + bv.w);
    uint2 o;
    o.x = *(uint32_t*)&h0;
    o.y = *(uint32_t*)&h1;
    *(uint2*)(out + (size_t)row * DMODEL + tid * 4) = o;
}

// ---------------------------------------------------------------------------
// fp16 tile loader: ROWS x 64 halves, row stride 144B
// ---------------------------------------------------------------------------
template <int ROWS, int NT>
__device__ __forceinline__ void tile_load(uint32_t dst, const __half* src,
                                          int ldK, int tid) {
    #pragma unroll
    for (int i = 0; i < ROWS * 8 / NT; i++) {
        int c = i * NT + tid;
        int m = c >> 3, q = c & 7;
        CPA16(dst + (uint32_t)(m * 144 + q * 16), src + (size_t)m * ldK + q * 8);
    }
}

// ---------------------------------------------------------------------------
// fp16 GEMM (R9-exact): warp tile 32x32, 8 warps, 2-stage cp.async.
//   EPI 2: +bias+res(fp32)->fp32 | 3: gelu->fp16 | 4: qkv|gate mixed ->fp16
// ---------------------------------------------------------------------------
template <int BM, int BN, int WM, int WN, int EPI, bool OUTH>
__global__ void __launch_bounds__(WM * WN * 32, 4)
hgemm(const __half* __restrict__ A, const __half* __restrict__ Bt,
      const float* __restrict__ bias, const float* __restrict__ res,
      void* __restrict__ Cv, int N, int K) {
    constexpr int NT = WM * WN * 32;
    constexpr int MI = BM / WM / 16;
    constexpr int NI = BN / WN / 8;
    constexpr int NJ = NI / 2;
    constexpr uint32_t ASTAGE = BM * 144;
    constexpr uint32_t BSTAGE = BN * 144;

    extern __shared__ char dsm[];

    const int tid  = threadIdx.x;
    const int warp = tid >> 5, lane = tid & 31;
    const int g    = lane >> 2, t4 = lane & 3;
    const int warpM = (warp / WN) * (BM / WM);
    const int warpN = (warp % WN) * (BN / WN);
    const int rowBase = blockIdx.y * BM;
    const int colBase = blockIdx.x * BN;

    const uint32_t smA = smem_u32(dsm);
    const uint32_t smB = smA + 2 * ASTAGE;
    const uint32_t aLds = smA + (uint32_t)((warpM + (lane & 15)) * 144 + (lane >> 4) * 16);
    const uint32_t bLds = smB + (uint32_t)((warpN + (lane & 15)) * 144 + (lane >> 4) * 16);

    const __half* Ag = A + (size_t)rowBase * K;
    const __half* Bg = Bt + (size_t)colBase * K;

    float acc[MI][NI][4];
    #pragma unroll
    for (int mi = 0; mi < MI; mi++)
        #pragma unroll
        for (int ni = 0; ni < NI; ni++)
            #pragma unroll
            for (int r = 0; r < 4; r++) acc[mi][ni][r] = 0.f;

    const int KT = K / 64;
    tile_load<BM, NT>(smA, Ag, K, tid);
    tile_load<BN, NT>(smB, Bg, K, tid);
    asm volatile("cp.async.commit_group;\n");

    for (int kt = 0; kt < KT; kt++) {
        asm volatile("cp.async.wait_group 0;\n");
        __syncthreads();

        if (kt + 1 < KT) {
            const uint32_t nb = (uint32_t)((kt + 1) & 1);
            tile_load<BM, NT>(smA + nb * ASTAGE, Ag + (kt + 1) * 64, K, tid);
            tile_load<BN, NT>(smB + nb * BSTAGE, Bg + (kt + 1) * 64, K, tid);
            asm volatile("cp.async.commit_group;\n");
        }

        const uint32_t aOff = aLds + (uint32_t)(kt & 1) * ASTAGE;
        const uint32_t bOff = bLds + (uint32_t)(kt & 1) * BSTAGE;
        #pragma unroll
        for (int ks = 0; ks < 4; ks++) {
            uint32_t af[MI][4], bf[NJ][4];
            #pragma unroll
            for (int mi = 0; mi < MI; mi++)
                LDSM_X4(af[mi][0], af[mi][1], af[mi][2], af[mi][3],
                        aOff + (uint32_t)(mi * 16 * 144 + ks * 32));
            #pragma unroll
            for (int nj = 0; nj < NJ; nj++)
                LDSM_X4(bf[nj][0], bf[nj][1], bf[nj][2], bf[nj][3],
                        bOff + (uint32_t)(nj * 16 * 144 + ks * 32));
            #pragma unroll
            for (int mi = 0; mi < MI; mi++)
                #pragma unroll
                for (int nj = 0; nj < NJ; nj++) {
                    asm volatile(
                        "mma.sync.aligned.m16n8k16.row.col.f32.f16.f16.f32 "
                        "{%0,%1,%2,%3}, {%4,%5,%6,%7}, {%8,%9}, {%0,%1,%2,%3};\n"
                        : "+f"(acc[mi][2*nj][0]), "+f"(acc[mi][2*nj][1]),
                          "+f"(acc[mi][2*nj][2]), "+f"(acc[mi][2*nj][3])
                        : "r"(af[mi][0]), "r"(af[mi][1]), "r"(af[mi][2]), "r"(af[mi][3]),
                          "r"(bf[nj][0]), "r"(bf[nj][2]));
                    asm volatile(
                        "mma.sync.aligned.m16n8k16.row.col.f32.f16.f16.f32 "
                        "{%0,%1,%2,%3}, {%4,%5,%6,%7}, {%8,%9}, {%0,%1,%2,%3};\n"
                        : "+f"(acc[mi][2*nj+1][0]), "+f"(acc[mi][2*nj+1][1]),
                          "+f"(acc[mi][2*nj+1][2]), "+f"(acc[mi][2*nj+1][3])
                        : "r"(af[mi][0]), "r"(af[mi][1]), "r"(af[mi][2]), "r"(af[mi][3]),
                          "r"(bf[nj][1]), "r"(bf[nj][3]));
                }
        }
        __syncthreads();
    }

    const bool sig = (EPI == 4) && (colBase >= D3);
    #pragma unroll
    for (int mi = 0; mi < MI; mi++) {
        #pragma unroll
        for (int ni = 0; ni < NI; ni++) {
            int row = rowBase + warpM + mi * 16 + g;
            int col = colBase + warpN + ni * 8 + t4 * 2;
            float b0 = bias[col], b1 = bias[col + 1];
            #pragma unroll
            for (int hh = 0; hh < 2; hh++) {
                int r = row + hh * 8;
                float vx = acc[mi][ni][hh * 2 + 0] + b0;
                float vy = acc[mi][ni][hh * 2 + 1] + b1;
                if (EPI == 3) {
                    vx = 0.5f * vx * (1.0f + erff(vx * 0.70710678118654752f));
                    vy = 0.5f * vy * (1.0f + erff(vy * 0.70710678118654752f));
                } else if (EPI == 4) {
                    if (sig) {
                        vx = 1.0f / (1.0f + __expf(-vx));
                        vy = 1.0f / (1.0f + __expf(-vy));
                    }
                }
                size_t off = (size_t)r * N + col;
                if (EPI == 2) {
                    float2 rr = *(const float2*)(res + off);
                    vx += rr.x; vy += rr.y;
                }
                if (OUTH) {
                    __half2 hv = __floats2half2_rn(vx, vy);
                    *(__half2*)((__half*)Cv + off) = hv;
                } else {
                    *(float2*)((float*)Cv + off) = make_float2(vx, vy);
                }
            }
        }
    }
}

// ---------------------------------------------------------------------------
// fc2 split-K GEMM: grid (8, 32, 2); z selects K-half; raw fp32 partials.
// ---------------------------------------------------------------------------
__global__ void __launch_bounds__(256, 4)
hgemm_sk(const __half* __restrict__ A, const __half* __restrict__ Bt) {
    constexpr int BM = 64, BN = 128, WN = 4;
    constexpr int NT = 256, MI = 2, NI = 4, NJ = 2;
    constexpr int LD = DFF;
    constexpr int KLEN = DFF / 2;
    constexpr uint32_t ASTAGE = BM * 144;
    constexpr uint32_t BSTAGE = BN * 144;

    extern __shared__ char dsm[];

    const int tid  = threadIdx.x;
    const int warp = tid >> 5, lane = tid & 31;
    const int g    = lane >> 2, t4 = lane & 3;
    const int warpM = (warp / WN) * 32;
    const int warpN = (warp % WN) * 32;
    const int rowBase = blockIdx.y * BM;
    const int colBase = blockIdx.x * BN;
    const int z = blockIdx.z;

    const uint32_t smA = smem_u32(dsm);
    const uint32_t smB = smA + 2 * ASTAGE;
    const uint32_t aLds = smA + (uint32_t)((warpM + (lane & 15)) * 144 + (lane >> 4) * 16);
    const uint32_t bLds = smB + (uint32_t)((warpN + (lane & 15)) * 144 + (lane >> 4) * 16);

    const __half* Ag = A + (size_t)rowBase * LD + z * KLEN;
    const __half* Bg = Bt + (size_t)colBase * LD + z * KLEN;
    float* Cp = g_part[z];

    float acc[MI][NI][4];
    #pragma unroll
    for (int mi = 0; mi < MI; mi++)
        #pragma unroll
        for (int ni = 0; ni < NI; ni++)
            #pragma unroll
            for (int r = 0; r < 4; r++) acc[mi][ni][r] = 0.f;

    const int KT = KLEN / 64;
    tile_load<BM, NT>(smA, Ag, LD, tid);
    tile_load<BN, NT>(smB, Bg, LD, tid);
    asm volatile("cp.async.commit_group;\n");

    for (int kt = 0; kt < KT; kt++) {
        asm volatile("cp.async.wait_group 0;\n");
        __syncthreads();

        if (kt + 1 < KT) {
            const uint32_t nb = (uint32_t)((kt + 1) & 1);
            tile_load<BM, NT>(smA + nb * ASTAGE, Ag + (kt + 1) * 64, LD, tid);
            tile_load<BN, NT>(smB + nb * BSTAGE, Bg + (kt + 1) * 64, LD, tid);
            asm volatile("cp.async.commit_group;\n");
        }

        const uint32_t aOff = aLds + (uint32_t)(kt & 1) * ASTAGE;
        const uint32_t bOff = bLds + (uint32_t)(kt & 1) * BSTAGE;
        #pragma unroll
        for (int ks = 0; ks < 4; ks++) {
            uint32_t af[MI][4], bf[NJ][4];
            #pragma unroll
            for (int mi = 0; mi < MI; mi++)
                LDSM_X4(af[mi][0], af[mi][1], af[mi][2], af[mi][3],
                        aOff + (uint32_t)(mi * 16 * 144 + ks * 32));
            #pragma unroll
            for (int nj = 0; nj < NJ; nj++)
                LDSM_X4(bf[nj][0], bf[nj][1], bf[nj][2], bf[nj][3],
                        bOff + (uint32_t)(nj * 16 * 144 + ks * 32));
            #pragma unroll
            for (int mi = 0; mi < MI; mi++)
                #pragma unroll
                for (int nj = 0; nj < NJ; nj++) {
                    asm volatile(
                        "mma.sync.aligned.m16n8k16.row.col.f32.f16.f16.f32 "
                        "{%0,%1,%2,%3}, {%4,%5,%6,%7}, {%8,%9}, {%0,%1,%2,%3};\n"
                        : "+f"(acc[mi][2*nj][0]), "+f"(acc[mi][2*nj][1]),
                          "+f"(acc[mi][2*nj][2]), "+f"(acc[mi][2*nj][3])
                        : "r"(af[mi][0]), "r"(af[mi][1]), "r"(af[mi][2]), "r"(af[mi][3]),
                          "r"(bf[nj][0]), "r"(bf[nj][2]));
                    asm volatile(
                        "mma.sync.aligned.m16n8k16.row.col.f32.f16.f16.f32 "
                        "{%0,%1,%2,%3}, {%4,%5,%6,%7}, {%8,%9}, {%0,%1,%2,%3};\n"
                        : "+f"(acc[mi][2*nj+1][0]), "+f"(acc[mi][2*nj+1][1]),
                          "+f"(acc[mi][2*nj+1][2]), "+f"(acc[mi][2*nj+1][3])
                        : "r"(af[mi][0]), "r"(af[mi][1]), "r"(af[mi][2]), "r"(af[mi][3]),
                          "r"(bf[nj][1]), "r"(bf[nj][3]));
                }
        }
        __syncthreads();
    }

    #pragma unroll
    for (int mi = 0; mi < MI; mi++) {
        #pragma unroll
        for (int ni = 0; ni < NI; ni++) {
            int row = rowBase + warpM + mi * 16 + g;
            int col = colBase + warpN + ni * 8 + t4 * 2;
            #pragma unroll
            for (int hh = 0; hh < 2; hh++) {
                int r = row + hh * 8;
                *(float2*)(Cp + (size_t)r * DMODEL + col) =
                    make_float2(acc[mi][ni][hh * 2 + 0], acc[mi][ni][hh * 2 + 1]);
            }
        }
    }
}

// combine: out = x1 + bias + p0 + p1
__global__ void combine_kernel(const float* __restrict__ x1,
                               const float* __restrict__ bias,
                               float* __restrict__ out) {
    int i = blockIdx.x * 256 + threadIdx.x;
    int col = (i * 4) & (DMODEL - 1);
    const float* p0 = g_part[0];
    const float* p1 = g_part[1];
    float4 a = ((const float4*)x1)[i];
    float4 b = ((const float4*)p0)[i];
    float4 c = ((const float4*)p1)[i];
    float4 o;
    o.x = a.x + bias[col + 0] + (b.x + c.x);
    o.y = a.y + bias[col + 1] + (b.y + c.y);
    o.z = a.z + bias[col + 2] + (b.z + c.z);
    o.w = a.w + bias[col + 3] + (b.w + c.w);
    ((float4*)out)[i] = o;
}

// ---------------------------------------------------------------------------
// Offset attention on combined [q|k|v|gate] buffer (stride DQG).
// ---------------------------------------------------------------------------
__global__ void attn_kernel(const __half* __restrict__ qg,
                            const float* __restrict__ pos_bias,
                            __half* __restrict__ y) {
    int warp = blockIdx.x * (blockDim.x >> 5) + (threadIdx.x >> 5);
    int lane = threadIdx.x & 31;
    int h = warp >> 11;
    int n = warp & 2047;
    int j = lane & 7;
    int g = lane >> 3;

    const __half* qrow  = qg + (size_t)n * DQG + h * HDIM + j * 8;
    const __half* kbase = qg + DMODEL + h * HDIM + j * 8;
    const __half* vbase = qg + 2 * DMODEL + h * HDIM + j * 8;
    const __half* gbase = qg + 3 * DMODEL + h * HDIM + j * 8;

    uint4 qv = *(const uint4*)(qrow);
    float2 q0 = h2f2(qv.x), q1 = h2f2(qv.y), q2 = h2f2(qv.z), q3 = h2f2(qv.w);

    const float scale = 0.125f;
    float s[11];

    #pragma unroll
    for (int i = 0; i < 11; i++) {
        int o = i * 4 + g;
        int delta = c_offs[o];
        bool valid = (delta <= n);
        float p = 0.f;
        if (valid) {
            uint4 kv = *(const uint4*)(kbase + (size_t)(n - delta) * DQG);
            float2 k0 = h2f2(kv.x), k1 = h2f2(kv.y), k2 = h2f2(kv.z), k3 = h2f2(kv.w);
            p = q0.x * k0.x + q0.y * k0.y + q1.x * k1.x + q1.y * k1.y
              + q2.x * k2.x + q2.y * k2.y + q3.x * k3.x + q3.y * k3.y;
        }
        p += __shfl_xor_sync(0xffffffffu, p, 1);
        p += __shfl_xor_sync(0xffffffffu, p, 2);
        p += __shfl_xor_sync(0xffffffffu, p, 4);
        s[i] = valid ? p * scale + pos_bias[o * NHEAD + h] : -INFINITY;
    }

    float mx = s[0];
    #pragma unroll
    for (int i = 1; i < 11; i++) mx = fmaxf(mx, s[i]);
    mx = fmaxf(mx, __shfl_xor_sync(0xffffffffu, mx, 8));
    mx = fmaxf(mx, __shfl_xor_sync(0xffffffffu, mx, 16));

    float denom = 0.f;
    #pragma unroll
    for (int i = 0; i < 11; i++) {
        s[i] = __expf(s[i] - mx);
        denom += s[i];
    }
    denom += __shfl_xor_sync(0xffffffffu, denom, 8);
    denom += __shfl_xor_sync(0xffffffffu, denom, 16);

    float acc[8] = {0.f, 0.f, 0.f, 0.f, 0.f, 0.f, 0.f, 0.f};
    #pragma unroll
    for (int i = 0; i < 11; i++) {
        int o = i * 4 + g;
        int delta = c_offs[o];
        if (delta <= n) {
            uint4 vv = *(const uint4*)(vbase + (size_t)(n - delta) * DQG);
            float2 v0 = h2f2(vv.x), v1 = h2f2(vv.y), v2 = h2f2(vv.z), v3 = h2f2(vv.w);
            float w = s[i];
            acc[0] = fmaf(w, v0.x, acc[0]);
            acc[1] = fmaf(w, v0.y, acc[1]);
            acc[2] = fmaf(w, v1.x, acc[2]);
            acc[3] = fmaf(w, v1.y, acc[3]);
            acc[4] = fmaf(w, v2.x, acc[4]);
            acc[5] = fmaf(w, v2.y, acc[5]);
            acc[6] = fmaf(w, v3.x, acc[6]);
            acc[7] = fmaf(w, v3.y, acc[7]);
        }
    }
    #pragma unroll
    for (int d = 0; d < 8; d++) {
        acc[d] += __shfl_xor_sync(0xffffffffu, acc[d], 8);
        acc[d] += __shfl_xor_sync(0xffffffffu, acc[d], 16);
    }

    if (g == 0) {
        float inv = 1.0f / denom;
        uint4 gv = *(const uint4*)(gbase + (size_t)n * DQG);
        float2 g0 = h2f2(gv.x), g1 = h2f2(gv.y), g2 = h2f2(gv.z), g3 = h2f2(gv.w);
        __half2 o0 = __floats2half2_rn(acc[0] * inv * g0.x, acc[1] * inv * g0.y);
        __half2 o1 = __floats2half2_rn(acc[2] * inv * g1.x, acc[3] * inv * g1.y);
        __half2 o2 = __floats2half2_rn(acc[4] * inv * g2.x, acc[5] * inv * g2.y);
        __half2 o3 = __floats2half2_rn(acc[6] * inv * g3.x, acc[7] * inv * g3.y);
        uint4 ov;
        ov.x = *(uint32_t*)&o0; ov.y = *(uint32_t*)&o1;
        ov.z = *(uint32_t*)&o2; ov.w = *(uint32_t*)&o3;
        *(uint4*)(y + (size_t)n * DMODEL + h * HDIM + j * 8) = ov;
    }
}

// ---------------------------------------------------------------------------
// Launch
// ---------------------------------------------------------------------------
extern "C" void kernel_launch(void* const* d_in, const int* in_sizes, int n_in,
                              void* d_out, int out_size) {
    __half *s_xn, *s_qg, *s_y, *s_xn2, *s_h;
    float *s_x1, *s_bqg;
    __half *s_wqg, *s_wout, *s_wfc1, *s_wfc2;
    cudaGetSymbolAddress((void**)&s_xn,  g_xn);
    cudaGetSymbolAddress((void**)&s_qg,  g_qg);
    cudaGetSymbolAddress((void**)&s_y,   g_y);
    cudaGetSymbolAddress((void**)&s_x1,  g_x1);
    cudaGetSymbolAddress((void**)&s_xn2, g_xn2);
    cudaGetSymbolAddress((void**)&s_h,   g_h);
    cudaGetSymbolAddress((void**)&s_wqg, g_wqg);
    cudaGetSymbolAddress((void**)&s_wout,g_wout);
    cudaGetSymbolAddress((void**)&s_wfc1,g_wfc1);
    cudaGetSymbolAddress((void**)&s_wfc2,g_wfc2);
    cudaGetSymbolAddress((void**)&s_bqg, g_bqg);

    const float* x      = (const float*)d_in[0];
    const float* ln1_g  = (const float*)d_in[1];
    const float* ln1_b  = (const float*)d_in[2];
    const float* qkv_w  = (const float*)d_in[3];
    const float* qkv_b  = (const float*)d_in[4];
    const float* gate_w = (const float*)d_in[5];
    const float* gate_b = (const float*)d_in[6];
    const float* out_w  = (const float*)d_in[7];
    const float* out_b  = (const float*)d_in[8];
    const float* pbias  = (const float*)d_in[9];
    const float* ln2_g  = (const float*)d_in[10];
    const float* ln2_b  = (const float*)d_in[11];
    const float* fc1_w  = (const float*)d_in[12];
    const float* fc1_b  = (const float*)d_in[13];
    const float* fc2_w  = (const float*)d_in[14];
    const float* fc2_b  = (const float*)d_in[15];
    float* out = (float*)d_out;

    const int SM2 = 2 * (64 + 128) * 144;  // 55296 -> 4 CTAs/SM @256thr
    cudaFuncSetAttribute(hgemm<64,128,2,4,4,true >, cudaFuncAttributeMaxDynamicSharedMemorySize, SM2);
    cudaFuncSetAttribute(hgemm<64,128,2,4,3,true >, cudaFuncAttributeMaxDynamicSharedMemorySize, SM2);
    cudaFuncSetAttribute(hgemm<64,128,2,4,2,false>, cudaFuncAttributeMaxDynamicSharedMemorySize, SM2);
    cudaFuncSetAttribute(hgemm_sk, cudaFuncAttributeMaxDynamicSharedMemorySize, SM2);

    prep_kernel<<<6656, dim3(32, 8)>>>(qkv_w, gate_w, out_w, fc1_w, fc2_w);
    bias_cat<<<DQG / 256, 256>>>(qkv_b, gate_b);

    // 1) LN1 -> fp16
    ln_kernel<<<NSEQ, 256>>>(x, ln1_g, ln1_b, s_xn);
    // 2) [qkv|gate] = xn @ wqg + bqg (sigmoid on gate cols)
    hgemm<64,128,2,4,4,true><<<dim3(DQG / 128, NSEQ / 64), 256, SM2>>>(
        s_xn, s_wqg, s_bqg, nullptr, s_qg, DQG, DMODEL);
    // 3) attention (+gate)
    attn_kernel<<<(NSEQ * NHEAD) / 8, 256>>>(s_qg, pbias, s_y);
    // 4) x1 = x + y @ out_w + out_b
    hgemm<64,128,2,4,2,false><<<dim3(DMODEL / 128, NSEQ / 64), 256, SM2>>>(
        s_y, s_wout, out_b, x, s_x1, DMODEL, DMODEL);
    // 5) LN2 -> fp16
    ln_kernel<<<NSEQ, 256>>>(s_x1, ln2_g, ln2_b, s_xn2);
    // 6) h = gelu(xn2 @ fc1_w + fc1_b)
    hgemm<64,128,2,4,3,true><<<dim3(DFF / 128, NSEQ / 64), 256, SM2>>>(
        s_xn2, s_wfc1, fc1_b, nullptr, s_h, DFF, DMODEL);
    // 7a) fc2 split-K partials: 512 CTAs in one launch
    hgemm_sk<<<dim3(DMODEL / 128, NSEQ / 64, 2), 256, SM2>>>(s_h, s_wfc2);
    // 7b) out = x1 + fc2_b + p0 + p1
    combine_kernel<<<NSEQ * DMODEL / 4 / 256, 256>>>(s_x1, fc2_b, out);
}